// round 7
// baseline (speedup 1.0000x reference)
#include <cuda_runtime.h>
#include <cstdint>

constexpr int NTR = 4096;
constexpr int NTE = 2048;
constexpr int DIM = 16;
constexpr int BS  = 128;
constexpr int NB  = NTR / BS;   // 32

__device__ float g_L [(size_t)NTR * NTR];
__device__ float g_Ks[(size_t)NTR * NTE];   // fp32 Kstar (intact)
__device__ float g_V [(size_t)NTR * NTE];   // solved in place -> V
__device__ float g_invD[NB * BS * BS];      // fp32 diag-block inverses
__device__ float g_xs[NTR * DIM];
__device__ float g_ts[NTE * DIM];
__device__ float g_sqx[NTR];
__device__ float g_sqt[NTE];
__device__ float g_w[NTR];
__device__ float g_alpha[NTR];
__device__ float g_partM[8 * NTE];
__device__ float g_partV[8 * NTE];
__device__ float g_params[2];
__device__ float g_scale[DIM];

// ---------------- helpers ----------------
__device__ __forceinline__ float tf32r(float x) {
    uint32_t u; asm("cvt.rna.tf32.f32 %0, %1;" : "=r"(u) : "f"(x));
    return __uint_as_float(u);
}
__device__ __forceinline__ void mma_tf32(float* d, const uint32_t* a, const uint32_t* b) {
    asm volatile(
        "mma.sync.aligned.m16n8k8.row.col.f32.tf32.tf32.f32 "
        "{%0,%1,%2,%3},{%4,%5,%6,%7},{%8,%9},{%0,%1,%2,%3};"
        : "+f"(d[0]), "+f"(d[1]), "+f"(d[2]), "+f"(d[3])
        : "r"(a[0]), "r"(a[1]), "r"(a[2]), "r"(a[3]), "r"(b[0]), "r"(b[1]));
}
__device__ __forceinline__ void cpa16(uint32_t dst, const void* src) {
    asm volatile("cp.async.cg.shared.global [%0], [%1], 16;\n" :: "r"(dst), "l"(src));
}

// ---------------- prep / builders ----------------
__global__ void k_prep(const float* lsf2, const float* ll2, const float* lsn2) {
    int t = threadIdx.x;
    if (t == 0) { g_params[0] = expf(lsf2[0]); g_params[1] = expf(lsn2[0]); }
    if (t < DIM) g_scale[t] = sqrtf(0.5f * expf(-ll2[t]));
}

__global__ void k_scale(const float* __restrict__ in, float* __restrict__ out,
                        float* __restrict__ sq, int n) {
    int i = blockIdx.x * blockDim.x + threadIdx.x;
    if (i >= n) return;
    float s = 0.f;
#pragma unroll
    for (int d = 0; d < DIM; d++) {
        float v = in[i * DIM + d] * g_scale[d];
        out[i * DIM + d] = v;
        s += v * v;
    }
    sq[i] = s;
}

__global__ void k_build_knn() {
    __shared__ float A[32][DIM];
    __shared__ float B[32][DIM + 1];
    int bi = blockIdx.y * 32, bj = blockIdx.x * 32;
    int t = threadIdx.x;
    for (int idx = t; idx < 32 * DIM; idx += 256) {
        int r = idx / DIM, d = idx % DIM;
        A[r][d] = g_xs[(bi + r) * DIM + d];
        B[r][d] = g_xs[(bj + r) * DIM + d];
    }
    __syncthreads();
    float sf2 = g_params[0], sn2 = g_params[1];
    int tx = t & 31, ty = t >> 5;
    int j = bj + tx;
    float sqj = g_sqx[j];
#pragma unroll
    for (int q = 0; q < 4; q++) {
        int li = ty * 4 + q, i = bi + li;
        float dot = 0.f;
#pragma unroll
        for (int d = 0; d < DIM; d++) dot += A[li][d] * B[tx][d];
        float d2 = fmaxf(g_sqx[i] + sqj - 2.f * dot, 0.f);
        float v = sf2 * expf(-d2);
        if (i == j) v += sn2;
        g_L[(size_t)i * NTR + j] = v;
    }
}

__global__ void k_build_ks() {   // writes Ks AND its copy for the in-place solve
    __shared__ float A[32][DIM];
    __shared__ float B[32][DIM + 1];
    int bi = blockIdx.y * 32, bj = blockIdx.x * 32;
    int t = threadIdx.x;
    for (int idx = t; idx < 32 * DIM; idx += 256) {
        int r = idx / DIM, d = idx % DIM;
        A[r][d] = g_xs[(bi + r) * DIM + d];
        B[r][d] = g_ts[(bj + r) * DIM + d];
    }
    __syncthreads();
    float sf2 = g_params[0];
    int tx = t & 31, ty = t >> 5;
    int j = bj + tx;
    float sqj = g_sqt[j];
#pragma unroll
    for (int q = 0; q < 4; q++) {
        int li = ty * 4 + q, i = bi + li;
        float dot = 0.f;
#pragma unroll
        for (int d = 0; d < DIM; d++) dot += A[li][d] * B[tx][d];
        float d2 = fmaxf(g_sqx[i] + sqj - 2.f * dot, 0.f);
        float v = sf2 * expf(-d2);
        g_Ks[(size_t)i * NTE + j] = v;
        g_V [(size_t)i * NTE + j] = v;
    }
}

// =========== wavefront potrf(128) + fp32 triangular inverse (1 block) =======
__global__ void k_potrf(int kb) {
    extern __shared__ float sh[];
    float* S     = sh;                    // 128*129
    float* Mi    = S + 128 * 129;         // 128*129
    float* rdiag = Mi + 128 * 129;        // 128
    volatile int* vflg = (volatile int*)(rdiag + 128);   // 128
    const int t = threadIdx.x;            // 1024
    const int lane = t & 31, w = t >> 5;  // 32 warps
    float* src = g_L + (size_t)(kb * BS) * NTR + kb * BS;

    for (int idx = t; idx < 128 * 128; idx += 1024) {
        int r = idx >> 7, c = idx & 127;
        S [r * 129 + c] = src[(size_t)r * NTR + c];
        Mi[r * 129 + c] = (r == c) ? 1.f : 0.f;
    }
    if (t < 128) ((int*)vflg)[t] = 0;
    __syncthreads();

    // factorization: warp w owns columns w, w+32, w+64, w+96 (in order)
    for (int q = 0; q < 4; q++) {
        const int j = w + q * 32;
        const int i0 = j + lane, i1 = i0 + 32, i2 = i0 + 64, i3 = i0 + 96;
        float r0 = (i0 < 128) ? S[i0 * 129 + j] : 0.f;
        float r1 = (i1 < 128) ? S[i1 * 129 + j] : 0.f;
        float r2 = (i2 < 128) ? S[i2 * 129 + j] : 0.f;
        float r3 = (i3 < 128) ? S[i3 * 129 + j] : 0.f;
        for (int k = 0; k < j; k++) {
            if (lane == 0) { while (vflg[k] == 0) __nanosleep(20); }
            __syncwarp();
            asm volatile("" ::: "memory");
            float sjk = S[j * 129 + k];
            if (i0 < 128) r0 -= S[i0 * 129 + k] * sjk;
            if (i1 < 128) r1 -= S[i1 * 129 + k] * sjk;
            if (i2 < 128) r2 -= S[i2 * 129 + k] * sjk;
            if (i3 < 128) r3 -= S[i3 * 129 + k] * sjk;
        }
        float rsd = rsqrtf(__shfl_sync(0xffffffffu, r0, 0));
        r0 *= rsd; r1 *= rsd; r2 *= rsd; r3 *= rsd;
        if (i0 < 128) S[i0 * 129 + j] = r0;
        if (i1 < 128) S[i1 * 129 + j] = r1;
        if (i2 < 128) S[i2 * 129 + j] = r2;
        if (i3 < 128) S[i3 * 129 + j] = r3;
        if (lane == 0) rdiag[j] = rsd;
        __syncwarp();
        __threadfence_block();
        if (lane == 0) vflg[j] = 1;
    }
    __syncthreads();

    // inverse: warp w owns Mi columns w+32q; forward substitution, AXPY form
    for (int j = 0; j < 128; j++) {
        float rdj = rdiag[j];
#pragma unroll
        for (int q = 0; q < 4; q++) {
            int c = w + q * 32;
            if (j >= c) {
                float x = Mi[j * 129 + c] * rdj;
                if (lane == 0) Mi[j * 129 + c] = x;
#pragma unroll
                for (int m = 0; m < 4; m++) {
                    int i = j + 1 + lane + m * 32;
                    if (i < 128) Mi[i * 129 + c] -= S[i * 129 + j] * x;
                }
            }
        }
        __syncwarp();
    }
    __syncthreads();

    for (int idx = t; idx < 128 * 128; idx += 1024) {
        int r = idx >> 7, c = idx & 127;
        if (c <= r) src[(size_t)r * NTR + c] = S[r * 129 + c];
        g_invD[kb * BS * BS + idx] = (c <= r) ? Mi[r * 129 + c] : 0.f;
    }
}

// =========== FAST GEMM: cp.async 3-stage, inputs already tf32-rounded =======
template <int TB, int SYRK>
__global__ void __launch_bounds__(256, 2) k_gemm_async(
    const float* __restrict__ A, int lda,
    const float* __restrict__ B, int ldb,
    float* __restrict__ C, int ldc)
{
    if (SYRK && (blockIdx.y < blockIdx.x)) return;
    extern __shared__ float sm[];
    constexpr int ASTG = 128 * 20;
    constexpr int BSTG = TB ? 128 * 20 : 16 * 136;
    float* Ab = sm;
    float* Bb = sm + 3 * ASTG;
    const int row0 = blockIdx.y * 128, col0 = blockIdx.x * 128;
    const int t = threadIdx.x;
    const int lane = t & 31, wid = t >> 5;
    const int wm = wid & 3, wn = wid >> 2;
    const int g = lane >> 2, tig = lane & 3;
    const uint32_t smbase = (uint32_t)__cvta_generic_to_shared(sm);
    const int arow = t & 127, acp = t >> 7;
    const int bkk = t >> 4, bcq = t & 15;

    auto issue = [&](int s, int stg) {
        const int k0 = s * 16;
        const float* srcA = A + (size_t)(row0 + arow) * lda + k0 + acp * 8;
        uint32_t dstA = smbase + (uint32_t)(stg * ASTG + arow * 20 + acp * 8) * 4u;
        cpa16(dstA, srcA); cpa16(dstA + 16, srcA + 4);
        if (TB) {
            const float* srcB = B + (size_t)(col0 + arow) * ldb + k0 + acp * 8;
            uint32_t dstB = smbase + (uint32_t)(3 * ASTG + stg * BSTG + arow * 20 + acp * 8) * 4u;
            cpa16(dstB, srcB); cpa16(dstB + 16, srcB + 4);
        } else {
            const float* srcB = B + (size_t)(k0 + bkk) * ldb + col0 + bcq * 4;
            uint32_t dstB = smbase + (uint32_t)(3 * ASTG + stg * BSTG + bkk * 136 + bcq * 4) * 4u;
            cpa16(dstB, srcB); cpa16(dstB + 256, srcB + 64);
        }
        asm volatile("cp.async.commit_group;\n");
    };

    float acc[2][8][4];
#pragma unroll
    for (int i = 0; i < 2; i++)
#pragma unroll
        for (int j = 0; j < 8; j++)
#pragma unroll
            for (int q = 0; q < 4; q++) acc[i][j][q] = 0.f;

    issue(0, 0); issue(1, 1);
#pragma unroll
    for (int s = 0; s < 8; s++) {
        if (s < 7) asm volatile("cp.async.wait_group 1;\n");
        else       asm volatile("cp.async.wait_group 0;\n");
        __syncthreads();
        if (s + 2 < 8) issue(s + 2, (s + 2) % 3);
        const float* Asb = Ab + (s % 3) * ASTG;
        const float* Bsb = Bb + (s % 3) * BSTG;
#pragma unroll
        for (int kf = 0; kf < 2; kf++) {
            const int kb = kf * 8;
            uint32_t a[2][4], b[8][2];
#pragma unroll
            for (int mt = 0; mt < 2; mt++) {
                int rb = wm * 32 + mt * 16 + g;
                a[mt][0] = __float_as_uint(Asb[rb * 20 + kb + tig]);
                a[mt][1] = __float_as_uint(Asb[(rb + 8) * 20 + kb + tig]);
                a[mt][2] = __float_as_uint(Asb[rb * 20 + kb + tig + 4]);
                a[mt][3] = __float_as_uint(Asb[(rb + 8) * 20 + kb + tig + 4]);
            }
#pragma unroll
            for (int nt = 0; nt < 8; nt++) {
                int cb = wn * 64 + nt * 8 + g;
                if (TB) {
                    b[nt][0] = __float_as_uint(Bsb[cb * 20 + kb + tig]);
                    b[nt][1] = __float_as_uint(Bsb[cb * 20 + kb + tig + 4]);
                } else {
                    b[nt][0] = __float_as_uint(Bsb[(kb + tig) * 136 + cb]);
                    b[nt][1] = __float_as_uint(Bsb[(kb + tig + 4) * 136 + cb]);
                }
            }
#pragma unroll
            for (int mt = 0; mt < 2; mt++)
#pragma unroll
                for (int nt = 0; nt < 8; nt++)
                    mma_tf32(acc[mt][nt], a[mt], b[nt]);
        }
        __syncthreads();
    }
#pragma unroll
    for (int mt = 0; mt < 2; mt++) {
        int r0 = row0 + wm * 32 + mt * 16 + g;
#pragma unroll
        for (int nt = 0; nt < 8; nt++) {
            int c = col0 + wn * 64 + nt * 8 + tig * 2;
            float2* p0 = (float2*)(C + (size_t)r0 * ldc + c);
            float2* p1 = (float2*)(C + (size_t)(r0 + 8) * ldc + c);
            float2 v0 = *p0, v1 = *p1;
            v0.x -= acc[mt][nt][0]; v0.y -= acc[mt][nt][1];
            v1.x -= acc[mt][nt][2]; v1.y -= acc[mt][nt][3];
            *p0 = v0; *p1 = v1;
        }
    }
}

// ====== CVT GEMM: C = rna(A*op(B)); inputs rounded at staging ======
template <int TB>
__global__ void __launch_bounds__(256, 2) k_gemm_cvt(
    const float* __restrict__ A, int lda,
    const float* __restrict__ B, int ldb,
    float* __restrict__ C, int ldc)
{
    const int row0 = blockIdx.y * 128, col0 = blockIdx.x * 128;
    __shared__ float As[16][136];
    __shared__ float Bs[16][136];
    const int t = threadIdx.x;
    const int lane = t & 31, wid = t >> 5;
    const int wm = wid & 3, wn = wid >> 2;
    const int g = lane >> 2, tig = lane & 3;
    const int ra = t & 127, fa = t >> 7;
    const int kk = t >> 4, cq = t & 15;

    float acc[2][8][4];
#pragma unroll
    for (int i = 0; i < 2; i++)
#pragma unroll
        for (int j = 0; j < 8; j++)
#pragma unroll
            for (int q = 0; q < 4; q++) acc[i][j][q] = 0.f;

    for (int k0 = 0; k0 < 128; k0 += 16) {
        {
            const float* ap = A + (size_t)(row0 + ra) * lda + k0 + fa * 4;
            float4 v0 = *(const float4*)ap;
            float4 v1 = *(const float4*)(ap + 8);
            As[fa * 4 + 0][ra] = tf32r(v0.x); As[fa * 4 + 1][ra] = tf32r(v0.y);
            As[fa * 4 + 2][ra] = tf32r(v0.z); As[fa * 4 + 3][ra] = tf32r(v0.w);
            As[8 + fa * 4 + 0][ra] = tf32r(v1.x); As[8 + fa * 4 + 1][ra] = tf32r(v1.y);
            As[8 + fa * 4 + 2][ra] = tf32r(v1.z); As[8 + fa * 4 + 3][ra] = tf32r(v1.w);
        }
        if (TB) {
            const float* bp = B + (size_t)(col0 + ra) * ldb + k0 + fa * 4;
            float4 v0 = *(const float4*)bp;
            float4 v1 = *(const float4*)(bp + 8);
            Bs[fa * 4 + 0][ra] = tf32r(v0.x); Bs[fa * 4 + 1][ra] = tf32r(v0.y);
            Bs[fa * 4 + 2][ra] = tf32r(v0.z); Bs[fa * 4 + 3][ra] = tf32r(v0.w);
            Bs[8 + fa * 4 + 0][ra] = tf32r(v1.x); Bs[8 + fa * 4 + 1][ra] = tf32r(v1.y);
            Bs[8 + fa * 4 + 2][ra] = tf32r(v1.z); Bs[8 + fa * 4 + 3][ra] = tf32r(v1.w);
        } else {
            const float* bp = B + (size_t)(k0 + kk) * ldb + col0 + cq * 4;
            float4 v0 = *(const float4*)bp;
            float4 v1 = *(const float4*)(bp + 64);
            *(float4*)&Bs[kk][cq * 4] =
                make_float4(tf32r(v0.x), tf32r(v0.y), tf32r(v0.z), tf32r(v0.w));
            *(float4*)&Bs[kk][64 + cq * 4] =
                make_float4(tf32r(v1.x), tf32r(v1.y), tf32r(v1.z), tf32r(v1.w));
        }
        __syncthreads();
#pragma unroll
        for (int kf = 0; kf < 2; kf++) {
            const int kb = kf * 8;
            uint32_t a[2][4], b[8][2];
#pragma unroll
            for (int mt = 0; mt < 2; mt++) {
                int rb = wm * 32 + mt * 16;
                a[mt][0] = __float_as_uint(As[kb + tig][rb + g]);
                a[mt][1] = __float_as_uint(As[kb + tig][rb + g + 8]);
                a[mt][2] = __float_as_uint(As[kb + tig + 4][rb + g]);
                a[mt][3] = __float_as_uint(As[kb + tig + 4][rb + g + 8]);
            }
#pragma unroll
            for (int nt = 0; nt < 8; nt++) {
                int cb = wn * 64 + nt * 8;
                b[nt][0] = __float_as_uint(Bs[kb + tig][cb + g]);
                b[nt][1] = __float_as_uint(Bs[kb + tig + 4][cb + g]);
            }
#pragma unroll
            for (int mt = 0; mt < 2; mt++)
#pragma unroll
                for (int nt = 0; nt < 8; nt++)
                    mma_tf32(acc[mt][nt], a[mt], b[nt]);
        }
        __syncthreads();
    }
#pragma unroll
    for (int mt = 0; mt < 2; mt++) {
        int r0 = row0 + wm * 32 + mt * 16 + g;
#pragma unroll
        for (int nt = 0; nt < 8; nt++) {
            int c = col0 + wn * 64 + nt * 8 + tig * 2;
            *(float2*)(C + (size_t)r0 * ldc + c) =
                make_float2(tf32r(acc[mt][nt][0]), tf32r(acc[mt][nt][1]));
            *(float2*)(C + (size_t)(r0 + 8) * ldc + c) =
                make_float2(tf32r(acc[mt][nt][2]), tf32r(acc[mt][nt][3]));
        }
    }
}

// ====== fp32 left-looking chains: one launch per block ======
__global__ void k_chain_fwd(int kb, const float* __restrict__ y) {  // 1024 thr
    __shared__ float s[BS];
    const int t = threadIdx.x, lane = t & 31, w = t >> 5;
    const int jmax = kb * BS;
    const int r = w * 4;                       // warp handles rows r..r+3
#pragma unroll
    for (int q = 0; q < 4; q++) {
        int i = kb * BS + r + q;
        const float* row = g_L + (size_t)i * NTR;
        float a = 0.f;
        for (int j = lane; j < jmax; j += 32) a += row[j] * g_w[j];
#pragma unroll
        for (int o = 16; o; o >>= 1) a += __shfl_down_sync(0xffffffffu, a, o);
        if (lane == 0) s[r + q] = y[i] - a;
    }
    __syncthreads();
    if (t < BS) {
        const float* Mi = g_invD + kb * BS * BS + t * BS;
        float a = 0.f;
#pragma unroll 8
        for (int j = 0; j < BS; j++) a += Mi[j] * s[j];
        g_w[kb * BS + t] = a;
    }
}

__global__ void k_chain_bwd(int kb) {          // 128 thr
    __shared__ float s[BS];
    const int t = threadIdx.x;
    const int col = kb * BS + t;
    float a = 0.f;
#pragma unroll 8
    for (int i = (kb + 1) * BS; i < NTR; i++)
        a += g_L[(size_t)i * NTR + col] * g_alpha[i];
    s[t] = g_w[col] - a;
    __syncthreads();
    const float* Mi = g_invD + kb * BS * BS;
    float x = 0.f;
#pragma unroll 8
    for (int j = 0; j < BS; j++) x += Mi[j * BS + t] * s[j];
    g_alpha[col] = x;
}

// ---------------- reductions ----------------
__global__ void k_part_mean() {
    __shared__ float sa[512];
    int t = threadIdx.x;                 // 128
    int n0 = blockIdx.y * 512;
    for (int q = t; q < 512; q += 128) sa[q] = g_alpha[n0 + q];
    __syncthreads();
    int m = blockIdx.x * 128 + t;
    float s = 0.f;
    for (int q = 0; q < 512; q++) s += g_Ks[(size_t)(n0 + q) * NTE + m] * sa[q];
    g_partM[blockIdx.y * NTE + m] = s;
}

__global__ void k_part_var() {
    int t = threadIdx.x;
    int n0 = blockIdx.y * 512;
    int m = blockIdx.x * 128 + t;
    float s = 0.f;
    for (int q = 0; q < 512; q++) { float v = g_V[(size_t)(n0 + q) * NTE + m]; s += v * v; }
    g_partV[blockIdx.y * NTE + m] = s;
}

__global__ void k_finalize(float* out) {
    int m = blockIdx.x * 256 + threadIdx.x;
    if (m >= NTE) return;
    float sm = 0.f, sv = 0.f;
#pragma unroll
    for (int p = 0; p < 8; p++) { sm += g_partM[p * NTE + m]; sv += g_partV[p * NTE + m]; }
    out[m] = sm;
    out[NTE + m] = g_params[0] + g_params[1] - sv;
}

// ---------------- launch ----------------
extern "C" void kernel_launch(void* const* d_in, const int* in_sizes, int n_in,
                              void* d_out, int out_size)
{
    const float* train_x = (const float*)d_in[0];
    const float* train_y = (const float*)d_in[1];
    const float* test_x  = (const float*)d_in[2];
    const float* lsf2    = (const float*)d_in[3];
    const float* ll2     = (const float*)d_in[4];
    const float* lsn2    = (const float*)d_in[5];
    float* out = (float*)d_out;

    float *pL, *pV, *pInvD, *pXs, *pTs, *pSqx, *pSqt;
    cudaGetSymbolAddress((void**)&pL,    g_L);
    cudaGetSymbolAddress((void**)&pV,    g_V);
    cudaGetSymbolAddress((void**)&pInvD, g_invD);
    cudaGetSymbolAddress((void**)&pXs,   g_xs);
    cudaGetSymbolAddress((void**)&pTs,   g_ts);
    cudaGetSymbolAddress((void**)&pSqx,  g_sqx);
    cudaGetSymbolAddress((void**)&pSqt,  g_sqt);

    const int smem_potrf = (2 * 128 * 129 + 256) * sizeof(float);      // ~133 KB
    cudaFuncSetAttribute(k_potrf, cudaFuncAttributeMaxDynamicSharedMemorySize, smem_potrf);
    const int smem_syrk = 3 * (128 * 20 + 128 * 20) * sizeof(float);   // 61440
    const int smem_vupd = 3 * (128 * 20 + 16 * 136) * sizeof(float);   // 56832
    cudaFuncSetAttribute((const void*)k_gemm_async<1, 1>,
                         cudaFuncAttributeMaxDynamicSharedMemorySize, smem_syrk);
    cudaFuncSetAttribute((const void*)k_gemm_async<0, 0>,
                         cudaFuncAttributeMaxDynamicSharedMemorySize, smem_vupd);

    k_prep<<<1, 32>>>(lsf2, ll2, lsn2);
    k_scale<<<(NTR + 255) / 256, 256>>>(train_x, pXs, pSqx, NTR);
    k_scale<<<(NTE + 255) / 256, 256>>>(test_x,  pTs, pSqt, NTE);
    k_build_knn<<<dim3(NTR / 32, NTR / 32), 256>>>();
    k_build_ks <<<dim3(NTE / 32, NTR / 32), 256>>>();

    // ---- blocked Cholesky; panel trsm in place ----
    for (int kb = 0; kb < NB; kb++) {
        k_potrf<<<1, 1024, smem_potrf>>>(kb);
        int R = NTR - (kb + 1) * BS;
        if (R > 0) {
            float* panel = pL + (size_t)(kb + 1) * BS * NTR + (size_t)kb * BS;
            k_gemm_cvt<1><<<dim3(1, R / BS), 256>>>(
                panel, NTR, pInvD + kb * BS * BS, BS, panel, NTR);
            float* C22 = pL + (size_t)(kb + 1) * BS * (NTR + 1);
            k_gemm_async<1, 1><<<dim3(R / BS, R / BS), 256, smem_syrk>>>(
                panel, NTR, panel, NTR, C22, NTR);
        }
    }

    // ---- fp32 chains: w = L^{-1} y ; alpha = L^{-T} w ----
    for (int kb = 0; kb < NB; kb++)      k_chain_fwd<<<1, 1024>>>(kb, train_y);
    for (int kb = NB - 1; kb >= 0; kb--) k_chain_bwd<<<1, BS>>>(kb);

    // ---- V = L^{-1} Kstar (in place in g_V; g_Ks intact) ----
    for (int kb = 0; kb < NB; kb++) {
        float* vkb = pV + (size_t)kb * BS * NTE;
        k_gemm_cvt<0><<<dim3(NTE / 128, 1), 256>>>(
            pInvD + kb * BS * BS, BS, vkb, NTE, vkb, NTE);
        int R = NTR - (kb + 1) * BS;
        if (R > 0) {
            k_gemm_async<0, 0><<<dim3(NTE / 128, R / BS), 256, smem_vupd>>>(
                pL + (size_t)(kb + 1) * BS * NTR + (size_t)kb * BS, NTR,
                vkb, NTE,
                pV + (size_t)(kb + 1) * BS * NTE, NTE);
        }
    }

    k_part_mean<<<dim3(NTE / 128, 8), 128>>>();
    k_part_var <<<dim3(NTE / 128, 8), 128>>>();
    k_finalize <<<(NTE + 255) / 256, 256>>>(out);
}

// round 8
// speedup vs baseline: 3.5767x; 3.5767x over previous
#include <cuda_runtime.h>
#include <cstdint>

constexpr int NTR = 4096;
constexpr int NTE = 2048;
constexpr int DIM = 16;
constexpr int NIT = 14;          // Chebyshev iterations for alpha

// ---- device scratch ----
__device__ float g_K   [(size_t)NTR * NTR];   // fp32 K (exact; matvec + rowsum)
__device__ float g_Ktf [(size_t)NTR * NTR];   // tf32-rounded K (GEMM A)
__device__ float g_Ks  [(size_t)NTR * NTE];   // fp32 Kstar (mean dot)
__device__ float g_Kstf[(size_t)NTR * NTE];   // rounded Kstar (GEMM B, quad dots)
__device__ float g_Z1  [(size_t)NTR * NTE];
__device__ float g_Z2  [(size_t)NTR * NTE];
__device__ float g_Z3  [(size_t)NTR * NTE];
__device__ float g_xs[NTR * DIM];
__device__ float g_ts[NTE * DIM];
__device__ float g_sqx[NTR];
__device__ float g_sqt[NTE];
__device__ float g_rowsum[NTR];
__device__ float g_xv[NTR];                   // cheb solution (alpha)
__device__ float g_rv[NTR];                   // cheb residual
__device__ float g_da[NTR], g_db[NTR];        // cheb direction (double buffer)
__device__ float g_spec[4];                   // theta, delta, 1/theta
__device__ float g_poly[7];                   // s*a0..s*a6
__device__ float g_c1[NIT + 2], g_c2[NIT + 2];
__device__ float g_partM[8 * NTE];
__device__ float g_partD[8 * 7 * NTE];
__device__ float g_params[2];                 // sigmaf2, sigman2
__device__ float g_scale[DIM];

// ---- helpers ----
__device__ __forceinline__ float tf32r(float x) {
    uint32_t u; asm("cvt.rna.tf32.f32 %0, %1;" : "=r"(u) : "f"(x));
    return __uint_as_float(u);
}
__device__ __forceinline__ void mma_tf32(float* d, const uint32_t* a, const uint32_t* b) {
    asm volatile(
        "mma.sync.aligned.m16n8k8.row.col.f32.tf32.tf32.f32 "
        "{%0,%1,%2,%3},{%4,%5,%6,%7},{%8,%9},{%0,%1,%2,%3};"
        : "+f"(d[0]), "+f"(d[1]), "+f"(d[2]), "+f"(d[3])
        : "r"(a[0]), "r"(a[1]), "r"(a[2]), "r"(a[3]), "r"(b[0]), "r"(b[1]));
}
__device__ __forceinline__ void cpa16(uint32_t dst, const void* src) {
    asm volatile("cp.async.cg.shared.global [%0], [%1], 16;\n" :: "r"(dst), "l"(src));
}

// ---- prep / builders ----
__global__ void k_prep(const float* lsf2, const float* ll2, const float* lsn2) {
    int t = threadIdx.x;
    if (t == 0) { g_params[0] = expf(lsf2[0]); g_params[1] = expf(lsn2[0]); }
    if (t < DIM) g_scale[t] = sqrtf(0.5f * expf(-ll2[t]));
}

__global__ void k_scale(const float* __restrict__ in, float* __restrict__ out,
                        float* __restrict__ sq, int n) {
    int i = blockIdx.x * blockDim.x + threadIdx.x;
    if (i >= n) return;
    float s = 0.f;
#pragma unroll
    for (int d = 0; d < DIM; d++) {
        float v = in[i * DIM + d] * g_scale[d];
        out[i * DIM + d] = v;
        s += v * v;
    }
    sq[i] = s;
}

__global__ void k_build_knn() {
    __shared__ float A[32][DIM];
    __shared__ float B[32][DIM + 1];
    int bi = blockIdx.y * 32, bj = blockIdx.x * 32;
    int t = threadIdx.x;
    for (int idx = t; idx < 32 * DIM; idx += 256) {
        int r = idx / DIM, d = idx % DIM;
        A[r][d] = g_xs[(bi + r) * DIM + d];
        B[r][d] = g_xs[(bj + r) * DIM + d];
    }
    __syncthreads();
    float sf2 = g_params[0], sn2 = g_params[1];
    int tx = t & 31, ty = t >> 5;
    int j = bj + tx;
    float sqj = g_sqx[j];
#pragma unroll
    for (int q = 0; q < 4; q++) {
        int li = ty * 4 + q, i = bi + li;
        float dot = 0.f;
#pragma unroll
        for (int d = 0; d < DIM; d++) dot += A[li][d] * B[tx][d];
        float d2 = fmaxf(g_sqx[i] + sqj - 2.f * dot, 0.f);
        float v = sf2 * expf(-d2);
        if (i == j) v += sn2;
        g_K  [(size_t)i * NTR + j] = v;
        g_Ktf[(size_t)i * NTR + j] = tf32r(v);
    }
}

__global__ void k_build_ks() {
    __shared__ float A[32][DIM];
    __shared__ float B[32][DIM + 1];
    int bi = blockIdx.y * 32, bj = blockIdx.x * 32;
    int t = threadIdx.x;
    for (int idx = t; idx < 32 * DIM; idx += 256) {
        int r = idx / DIM, d = idx % DIM;
        A[r][d] = g_xs[(bi + r) * DIM + d];
        B[r][d] = g_ts[(bj + r) * DIM + d];
    }
    __syncthreads();
    float sf2 = g_params[0];
    int tx = t & 31, ty = t >> 5;
    int j = bj + tx;
    float sqj = g_sqt[j];
#pragma unroll
    for (int q = 0; q < 4; q++) {
        int li = ty * 4 + q, i = bi + li;
        float dot = 0.f;
#pragma unroll
        for (int d = 0; d < DIM; d++) dot += A[li][d] * B[tx][d];
        float d2 = fmaxf(g_sqx[i] + sqj - 2.f * dot, 0.f);
        float v = sf2 * expf(-d2);
        g_Ks  [(size_t)i * NTE + j] = v;
        g_Kstf[(size_t)i * NTE + j] = tf32r(v);
    }
}

// ---- row sums (deterministic, warp per row) ----
__global__ void k_rowsum() {
    int t = threadIdx.x, lane = t & 31, w = t >> 5;
    int row = blockIdx.x * 8 + w;
    const float* Kr = g_K + (size_t)row * NTR;
    float s = 0.f;
    for (int j = lane; j < NTR; j += 32) s += Kr[j];
#pragma unroll
    for (int o = 16; o; o >>= 1) s += __shfl_down_sync(0xffffffffu, s, o);
    if (lane == 0) g_rowsum[row] = s;
}

// ---- spectrum bounds -> Chebyshev poly coeffs + iteration schedule ----
__global__ void k_spec() {
    __shared__ float sm[1024];
    int t = threadIdx.x;
    float m = 0.f;
    for (int i = t; i < NTR; i += 1024) m = fmaxf(m, g_rowsum[i]);
    sm[t] = m;
    __syncthreads();
    for (int o = 512; o; o >>= 1) {
        if (t < o) sm[t] = fmaxf(sm[t], sm[t + o]);
        __syncthreads();
    }
    if (t == 0) {
        float b = sm[0];
        float sf2 = g_params[0], sn2 = g_params[1];
        float diag = sf2 + sn2;
        float a = fmaxf(sn2, 2.f * diag - b);
        if (!(a < b)) a = 0.5f * b;
        float theta = 0.5f * (a + b);
        float delta = fmaxf(0.5f * (b - a), 1e-6f * theta);
        float gamma = theta / delta;
        float rho   = 1.f / (gamma + sqrtf(gamma * gamma - 1.f));
        float r2 = rho * rho, r3 = r2 * rho, r4 = r2 * r2, r5 = r4 * rho, r6 = r4 * r2;
        float s = 2.f * rho / (delta * (1.f - r2));
        g_poly[0] = s * (1.f - 2.f * r2 + 2.f * r4 - 2.f * r6);
        g_poly[1] = s * (-2.f * rho + 6.f * r3 - 10.f * r5);
        g_poly[2] = s * (4.f * r2 - 16.f * r4 + 36.f * r6);
        g_poly[3] = s * (-8.f * r3 + 40.f * r5);
        g_poly[4] = s * (16.f * r4 - 96.f * r6);
        g_poly[5] = s * (-32.f * r5);
        g_poly[6] = s * (64.f * r6);
        g_spec[0] = theta; g_spec[1] = delta; g_spec[2] = 1.f / theta;
        float sig1 = gamma, rc = 1.f / sig1;
        for (int k = 1; k <= NIT + 1; k++) {
            float rn = 1.f / (2.f * sig1 - rc);
            g_c1[k] = rn * rc;
            g_c2[k] = 2.f * rn / delta;
            rc = rn;
        }
    }
}

// ---- big tensor GEMM: Z = tf32r((A*B - theta*B_at_C) / delta), NN, K-dim=4096
__global__ void __launch_bounds__(256, 2) k_gemmU(
    const float* __restrict__ A,     // g_Ktf, lda = NTR
    const float* __restrict__ B,     // rounded input, ldb = NTE
    float* __restrict__ Z)           // ldc = NTE
{
    extern __shared__ float sm[];
    constexpr int ASTG = 128 * 20;
    constexpr int BSTG = 16 * 136;
    constexpr int NS   = NTR / 16;   // 256 slices
    const int row0 = blockIdx.y * 128, col0 = blockIdx.x * 128;
    const int t = threadIdx.x;
    const int lane = t & 31, wid = t >> 5;
    const int wm = wid & 3, wn = wid >> 2;
    const int g = lane >> 2, tig = lane & 3;
    const uint32_t smbase = (uint32_t)__cvta_generic_to_shared(sm);
    const int arow = t & 127, acp = t >> 7;
    const int bkk = t >> 4, bcq = t & 15;
    const float theta = g_spec[0];
    const float idel  = 1.f / g_spec[1];

    auto issue = [&](int s, int stg) {
        const int k0 = s * 16;
        const float* srcA = A + (size_t)(row0 + arow) * NTR + k0 + acp * 8;
        uint32_t dstA = smbase + (uint32_t)(stg * ASTG + arow * 20 + acp * 8) * 4u;
        cpa16(dstA, srcA); cpa16(dstA + 16, srcA + 4);
        const float* srcB = B + (size_t)(k0 + bkk) * NTE + col0 + bcq * 4;
        uint32_t dstB = smbase + (uint32_t)(3 * ASTG + stg * BSTG + bkk * 136 + bcq * 4) * 4u;
        cpa16(dstB, srcB); cpa16(dstB + 256, srcB + 64);
        asm volatile("cp.async.commit_group;\n");
    };

    float acc[2][8][4];
#pragma unroll
    for (int i = 0; i < 2; i++)
#pragma unroll
        for (int j = 0; j < 8; j++)
#pragma unroll
            for (int q = 0; q < 4; q++) acc[i][j][q] = 0.f;

    issue(0, 0); issue(1, 1);
    int cur = 0, nxt = 2;
    for (int s = 0; s < NS; s++) {
        if (s < NS - 1) asm volatile("cp.async.wait_group 1;\n");
        else            asm volatile("cp.async.wait_group 0;\n");
        __syncthreads();
        if (s + 2 < NS) issue(s + 2, nxt);
        const float* Asb = sm + cur * ASTG;
        const float* Bsb = sm + 3 * ASTG + cur * BSTG;
#pragma unroll
        for (int kf = 0; kf < 2; kf++) {
            const int kb = kf * 8;
            uint32_t a[2][4], b[8][2];
#pragma unroll
            for (int mt = 0; mt < 2; mt++) {
                int rb = wm * 32 + mt * 16 + g;
                a[mt][0] = __float_as_uint(Asb[rb * 20 + kb + tig]);
                a[mt][1] = __float_as_uint(Asb[(rb + 8) * 20 + kb + tig]);
                a[mt][2] = __float_as_uint(Asb[rb * 20 + kb + tig + 4]);
                a[mt][3] = __float_as_uint(Asb[(rb + 8) * 20 + kb + tig + 4]);
            }
#pragma unroll
            for (int nt = 0; nt < 8; nt++) {
                int cb = wn * 64 + nt * 8 + g;
                b[nt][0] = __float_as_uint(Bsb[(kb + tig) * 136 + cb]);
                b[nt][1] = __float_as_uint(Bsb[(kb + tig + 4) * 136 + cb]);
            }
#pragma unroll
            for (int mt = 0; mt < 2; mt++)
#pragma unroll
                for (int nt = 0; nt < 8; nt++)
                    mma_tf32(acc[mt][nt], a[mt], b[nt]);
        }
        __syncthreads();
        cur = (cur == 2) ? 0 : cur + 1;
        nxt = (nxt == 2) ? 0 : nxt + 1;
    }

    // epilogue: Z = tf32r((acc - theta*B)/delta)
#pragma unroll
    for (int mt = 0; mt < 2; mt++) {
        int r0 = row0 + wm * 32 + mt * 16 + g;
#pragma unroll
        for (int nt = 0; nt < 8; nt++) {
            int c = col0 + wn * 64 + nt * 8 + tig * 2;
            float2 x0 = *(const float2*)(B + (size_t)r0 * NTE + c);
            float2 x1 = *(const float2*)(B + (size_t)(r0 + 8) * NTE + c);
            *(float2*)(Z + (size_t)r0 * NTE + c) = make_float2(
                tf32r((acc[mt][nt][0] - theta * x0.x) * idel),
                tf32r((acc[mt][nt][1] - theta * x0.y) * idel));
            *(float2*)(Z + (size_t)(r0 + 8) * NTE + c) = make_float2(
                tf32r((acc[mt][nt][2] - theta * x1.x) * idel),
                tf32r((acc[mt][nt][3] - theta * x1.y) * idel));
        }
    }
}

// ---- Chebyshev semi-iteration for alpha = K^{-1} y (pure fp32) ----
__global__ void k_cheb_init(const float* __restrict__ y) {
    int i = blockIdx.x * 256 + threadIdx.x;
    if (i >= NTR) return;
    g_xv[i] = 0.f;
    g_rv[i] = y[i];
    g_da[i] = y[i] * g_spec[2];
}

__global__ void k_cheb_iter(const float* __restrict__ din, float* __restrict__ dout, int k) {
    int t = threadIdx.x, lane = t & 31, w = t >> 5;
    int row = blockIdx.x * 8 + w;
    const float* Kr = g_K + (size_t)row * NTR;
    float s = 0.f;
    for (int j = lane; j < NTR; j += 32) s += Kr[j] * din[j];
#pragma unroll
    for (int o = 16; o; o >>= 1) s += __shfl_down_sync(0xffffffffu, s, o);
    if (lane == 0) {
        float dv = din[row];
        g_xv[row] += dv;
        float rv = g_rv[row] - s;
        g_rv[row] = rv;
        dout[row] = g_c1[k] * dv + g_c2[k] * rv;
    }
}

__global__ void k_axpy_final(const float* __restrict__ d) {
    int i = blockIdx.x * 256 + threadIdx.x;
    if (i < NTR) g_xv[i] += d[i];
}

// ---- fused dots: mean partial + 7 moment partials ----
__global__ void k_dots() {            // grid (NTE/128, 8), 128 threads
    __shared__ float sa[512];
    int t = threadIdx.x;
    int n0 = blockIdx.y * 512;
    for (int q = t; q < 512; q += 128) sa[q] = g_xv[n0 + q];
    __syncthreads();
    int m = blockIdx.x * 128 + t;
    float dm = 0, d00 = 0, d01 = 0, d11 = 0, d12 = 0, d22 = 0, d23 = 0, d33 = 0;
    for (int q = 0; q < 512; q++) {
        size_t off = (size_t)(n0 + q) * NTE + m;
        float kf = g_Ks[off];
        float kh = g_Kstf[off];
        float z1 = g_Z1[off], z2 = g_Z2[off], z3 = g_Z3[off];
        dm  += kf * sa[q];
        d00 += kh * kh; d01 += kh * z1; d11 += z1 * z1;
        d12 += z1 * z2; d22 += z2 * z2; d23 += z2 * z3; d33 += z3 * z3;
    }
    g_partM[blockIdx.y * NTE + m] = dm;
    float* pd = g_partD + (size_t)blockIdx.y * 7 * NTE + m;
    pd[0 * NTE] = d00; pd[1 * NTE] = d01; pd[2 * NTE] = d11; pd[3 * NTE] = d12;
    pd[4 * NTE] = d22; pd[5 * NTE] = d23; pd[6 * NTE] = d33;
}

__global__ void k_finalize(float* out) {
    int m = blockIdx.x * 256 + threadIdx.x;
    if (m >= NTE) return;
    float sm = 0.f, D[7] = {0, 0, 0, 0, 0, 0, 0};
    for (int p = 0; p < 8; p++) {
        sm += g_partM[p * NTE + m];
        const float* pd = g_partD + (size_t)p * 7 * NTE + m;
#pragma unroll
        for (int j = 0; j < 7; j++) D[j] += pd[j * NTE];
    }
    float q = 0.f;
#pragma unroll
    for (int j = 0; j < 7; j++) q += g_poly[j] * D[j];
    out[m] = sm;
    out[NTE + m] = g_params[0] + g_params[1] - q;
}

// ---- launch ----
extern "C" void kernel_launch(void* const* d_in, const int* in_sizes, int n_in,
                              void* d_out, int out_size)
{
    const float* train_x = (const float*)d_in[0];
    const float* train_y = (const float*)d_in[1];
    const float* test_x  = (const float*)d_in[2];
    const float* lsf2    = (const float*)d_in[3];
    const float* ll2     = (const float*)d_in[4];
    const float* lsn2    = (const float*)d_in[5];
    float* out = (float*)d_out;

    float *pKtf, *pKstf, *pZ1, *pZ2, *pZ3, *pXs, *pTs, *pSqx, *pSqt, *pDa, *pDb;
    cudaGetSymbolAddress((void**)&pKtf,  g_Ktf);
    cudaGetSymbolAddress((void**)&pKstf, g_Kstf);
    cudaGetSymbolAddress((void**)&pZ1,   g_Z1);
    cudaGetSymbolAddress((void**)&pZ2,   g_Z2);
    cudaGetSymbolAddress((void**)&pZ3,   g_Z3);
    cudaGetSymbolAddress((void**)&pXs,   g_xs);
    cudaGetSymbolAddress((void**)&pTs,   g_ts);
    cudaGetSymbolAddress((void**)&pSqx,  g_sqx);
    cudaGetSymbolAddress((void**)&pSqt,  g_sqt);
    cudaGetSymbolAddress((void**)&pDa,   g_da);
    cudaGetSymbolAddress((void**)&pDb,   g_db);

    const int smem_gemm = 3 * (128 * 20 + 16 * 136) * sizeof(float);  // 56832
    cudaFuncSetAttribute(k_gemmU, cudaFuncAttributeMaxDynamicSharedMemorySize, smem_gemm);

    k_prep<<<1, 32>>>(lsf2, ll2, lsn2);
    k_scale<<<(NTR + 255) / 256, 256>>>(train_x, pXs, pSqx, NTR);
    k_scale<<<(NTE + 255) / 256, 256>>>(test_x,  pTs, pSqt, NTE);
    k_build_knn<<<dim3(NTR / 32, NTR / 32), 256>>>();
    k_build_ks <<<dim3(NTE / 32, NTR / 32), 256>>>();
    k_rowsum<<<NTR / 8, 256>>>();
    k_spec<<<1, 1024>>>();

    // variance path: Z1 = U*Ks, Z2 = U*Z1, Z3 = U*Z2  (three big GEMMs)
    dim3 ggrid(NTE / 128, NTR / 128);
    k_gemmU<<<ggrid, 256, smem_gemm>>>(pKtf, pKstf, pZ1);
    k_gemmU<<<ggrid, 256, smem_gemm>>>(pKtf, pZ1,   pZ2);
    k_gemmU<<<ggrid, 256, smem_gemm>>>(pKtf, pZ2,   pZ3);

    // mean path: alpha = K^{-1} y via Chebyshev semi-iteration (fp32)
    k_cheb_init<<<(NTR + 255) / 256, 256>>>(train_y);
    float* din = pDa;
    float* dou = pDb;
    for (int k = 1; k <= NIT; k++) {
        k_cheb_iter<<<NTR / 8, 256>>>(din, dou, k);
        float* tmp = din; din = dou; dou = tmp;
    }
    k_axpy_final<<<(NTR + 255) / 256, 256>>>(din);

    k_dots<<<dim3(NTE / 128, 8), 128>>>();
    k_finalize<<<(NTE + 255) / 256, 256>>>(out);
}

// round 9
// speedup vs baseline: 5.8753x; 1.6427x over previous
#include <cuda_runtime.h>
#include <cstdint>

constexpr int NTR = 4096;
constexpr int NTE = 2048;
constexpr int DIM = 16;
constexpr int NIT = 12;          // Chebyshev iterations for alpha

// ---- device scratch ----
__device__ float g_K   [(size_t)NTR * NTR];   // fp32 K (matvec + rowsum)
__device__ float g_Ktf [(size_t)NTR * NTR];   // tf32-rounded K (GEMM A)
__device__ float g_Ks  [(size_t)NTR * NTE];   // fp32 Kstar (dots)
__device__ float g_Kstf[(size_t)NTR * NTE];   // rounded Kstar (GEMM-1 B operand)
__device__ float g_Z1  [(size_t)NTR * NTE];
__device__ float g_Z2  [(size_t)NTR * NTE];
__device__ float g_xs[NTR * DIM];
__device__ float g_ts[NTE * DIM];
__device__ float g_sqx[NTR];
__device__ float g_sqt[NTE];
__device__ float g_rowsum[NTR];
__device__ float g_xv[NTR];                   // cheb solution (alpha)
__device__ float g_rv[NTR];                   // cheb residual
__device__ float g_da[NTR], g_db[NTR];        // cheb direction (double buffer)
__device__ float g_spec[4];                   // theta, delta, 1/theta
__device__ float g_poly[5];                   // s*a0..s*a4 (degree 4)
__device__ float g_c1[NIT + 2], g_c2[NIT + 2];
__device__ float g_partM[8 * NTE];
__device__ float g_partD[8 * 5 * NTE];
__device__ float g_params[2];                 // sigmaf2, sigman2
__device__ float g_scale[DIM];

// ---- helpers ----
__device__ __forceinline__ float tf32r(float x) {
    uint32_t u; asm("cvt.rna.tf32.f32 %0, %1;" : "=r"(u) : "f"(x));
    return __uint_as_float(u);
}
__device__ __forceinline__ void mma_tf32(float* d, const uint32_t* a, const uint32_t* b) {
    asm volatile(
        "mma.sync.aligned.m16n8k8.row.col.f32.tf32.tf32.f32 "
        "{%0,%1,%2,%3},{%4,%5,%6,%7},{%8,%9},{%0,%1,%2,%3};"
        : "+f"(d[0]), "+f"(d[1]), "+f"(d[2]), "+f"(d[3])
        : "r"(a[0]), "r"(a[1]), "r"(a[2]), "r"(a[3]), "r"(b[0]), "r"(b[1]));
}
__device__ __forceinline__ void cpa16(uint32_t dst, const void* src) {
    asm volatile("cp.async.cg.shared.global [%0], [%1], 16;\n" :: "r"(dst), "l"(src));
}

// ---- prep / builders ----
__global__ void k_prep(const float* lsf2, const float* ll2, const float* lsn2) {
    int t = threadIdx.x;
    if (t == 0) { g_params[0] = expf(lsf2[0]); g_params[1] = expf(lsn2[0]); }
    if (t < DIM) g_scale[t] = sqrtf(0.5f * expf(-ll2[t]));
}

__global__ void k_scale(const float* __restrict__ in, float* __restrict__ out,
                        float* __restrict__ sq, int n) {
    int i = blockIdx.x * blockDim.x + threadIdx.x;
    if (i >= n) return;
    float s = 0.f;
#pragma unroll
    for (int d = 0; d < DIM; d++) {
        float v = in[i * DIM + d] * g_scale[d];
        out[i * DIM + d] = v;
        s += v * v;
    }
    sq[i] = s;
}

__global__ void k_build_knn() {
    __shared__ float A[32][DIM];
    __shared__ float B[32][DIM + 1];
    int bi = blockIdx.y * 32, bj = blockIdx.x * 32;
    int t = threadIdx.x;
    for (int idx = t; idx < 32 * DIM; idx += 256) {
        int r = idx / DIM, d = idx % DIM;
        A[r][d] = g_xs[(bi + r) * DIM + d];
        B[r][d] = g_xs[(bj + r) * DIM + d];
    }
    __syncthreads();
    float sf2 = g_params[0], sn2 = g_params[1];
    int tx = t & 31, ty = t >> 5;
    int j = bj + tx;
    float sqj = g_sqx[j];
#pragma unroll
    for (int q = 0; q < 4; q++) {
        int li = ty * 4 + q, i = bi + li;
        float dot = 0.f;
#pragma unroll
        for (int d = 0; d < DIM; d++) dot += A[li][d] * B[tx][d];
        float d2 = fmaxf(g_sqx[i] + sqj - 2.f * dot, 0.f);
        float v = sf2 * expf(-d2);
        if (i == j) v += sn2;
        g_K  [(size_t)i * NTR + j] = v;
        g_Ktf[(size_t)i * NTR + j] = tf32r(v);
    }
}

__global__ void k_build_ks() {
    __shared__ float A[32][DIM];
    __shared__ float B[32][DIM + 1];
    int bi = blockIdx.y * 32, bj = blockIdx.x * 32;
    int t = threadIdx.x;
    for (int idx = t; idx < 32 * DIM; idx += 256) {
        int r = idx / DIM, d = idx % DIM;
        A[r][d] = g_xs[(bi + r) * DIM + d];
        B[r][d] = g_ts[(bj + r) * DIM + d];
    }
    __syncthreads();
    float sf2 = g_params[0];
    int tx = t & 31, ty = t >> 5;
    int j = bj + tx;
    float sqj = g_sqt[j];
#pragma unroll
    for (int q = 0; q < 4; q++) {
        int li = ty * 4 + q, i = bi + li;
        float dot = 0.f;
#pragma unroll
        for (int d = 0; d < DIM; d++) dot += A[li][d] * B[tx][d];
        float d2 = fmaxf(g_sqx[i] + sqj - 2.f * dot, 0.f);
        float v = sf2 * expf(-d2);
        g_Ks  [(size_t)i * NTE + j] = v;
        g_Kstf[(size_t)i * NTE + j] = tf32r(v);
    }
}

// ---- row sums (deterministic, warp per row) ----
__global__ void k_rowsum() {
    int t = threadIdx.x, lane = t & 31, w = t >> 5;
    int row = blockIdx.x * 8 + w;
    const float* Kr = g_K + (size_t)row * NTR;
    float s = 0.f;
    for (int j = lane; j < NTR; j += 32) s += Kr[j];
#pragma unroll
    for (int o = 16; o; o >>= 1) s += __shfl_down_sync(0xffffffffu, s, o);
    if (lane == 0) g_rowsum[row] = s;
}

// ---- spectrum bounds -> degree-4 poly coeffs + cheb schedule ----
__global__ void k_spec() {
    __shared__ float sm[1024];
    int t = threadIdx.x;
    float m = 0.f;
    for (int i = t; i < NTR; i += 1024) m = fmaxf(m, g_rowsum[i]);
    sm[t] = m;
    __syncthreads();
    for (int o = 512; o; o >>= 1) {
        if (t < o) sm[t] = fmaxf(sm[t], sm[t + o]);
        __syncthreads();
    }
    if (t == 0) {
        float b = sm[0];
        float sf2 = g_params[0], sn2 = g_params[1];
        float diag = sf2 + sn2;
        float a = fmaxf(sn2, 2.f * diag - b);
        if (!(a < b)) a = 0.5f * b;
        float theta = 0.5f * (a + b);
        float delta = fmaxf(0.5f * (b - a), 1e-6f * theta);
        float gamma = theta / delta;
        float rho   = 1.f / (gamma + sqrtf(gamma * gamma - 1.f));
        float r2 = rho * rho, r3 = r2 * rho, r4 = r2 * r2;
        float s = 2.f * rho / (delta * (1.f - r2));
        g_poly[0] = s * (1.f - 2.f * r2 + 2.f * r4);
        g_poly[1] = s * (-2.f * rho + 6.f * r3);
        g_poly[2] = s * (4.f * r2 - 16.f * r4);
        g_poly[3] = s * (-8.f * r3);
        g_poly[4] = s * (16.f * r4);
        g_spec[0] = theta; g_spec[1] = delta; g_spec[2] = 1.f / theta;
        float sig1 = gamma, rc = 1.f / sig1;
        for (int k = 1; k <= NIT + 1; k++) {
            float rn = 1.f / (2.f * sig1 - rc);
            g_c1[k] = rn * rc;
            g_c2[k] = 2.f * rn / delta;
            rc = rn;
        }
    }
}

// ---- big tensor GEMM: Z = tf32r((A*B - theta*B) / delta), NN, K-dim=4096 ----
// 128 threads, warp grid 2x2, warp tile 64x64 (MT=4, NT=8): 1.5x better MMA:LDS
__global__ void __launch_bounds__(128, 2) k_gemmU(
    const float* __restrict__ A,     // g_Ktf, lda = NTR
    const float* __restrict__ B,     // rounded input, ldb = NTE
    float* __restrict__ Z)           // ldc = NTE
{
    extern __shared__ float sm[];
    constexpr int ASTG = 128 * 20;
    constexpr int BSTG = 16 * 136;
    constexpr int NS   = NTR / 16;   // 256 slices
    const int row0 = blockIdx.y * 128, col0 = blockIdx.x * 128;
    const int t = threadIdx.x;
    const int lane = t & 31, wid = t >> 5;
    const int wm = wid & 1, wn = wid >> 1;     // 2 x 2 warp grid
    const int g = lane >> 2, tig = lane & 3;
    const uint32_t smbase = (uint32_t)__cvta_generic_to_shared(sm);
    const int bkk = t >> 3, bcq = t & 7;       // B staging: 16 rows x 8 col-chunks
    const float theta = g_spec[0];
    const float idel  = 1.f / g_spec[1];

    auto issue = [&](int s, int stg) {
        const int k0 = s * 16;
        // A: thread t stages row (row0+t), 16 k-floats -> [m][k] pad 20
        const float* srcA = A + (size_t)(row0 + t) * NTR + k0;
        uint32_t dstA = smbase + (uint32_t)(stg * ASTG + t * 20) * 4u;
#pragma unroll
        for (int j = 0; j < 4; j++) cpa16(dstA + j * 16, srcA + j * 4);
        // B: [k][n] pad 136; each thread 4x 16B chunks across 128 cols
        const float* srcB = B + (size_t)(k0 + bkk) * NTE + col0 + bcq * 4;
        uint32_t dstB = smbase + (uint32_t)(3 * ASTG + stg * BSTG + bkk * 136 + bcq * 4) * 4u;
#pragma unroll
        for (int j = 0; j < 4; j++) cpa16(dstB + j * 128, srcB + j * 32);
        asm volatile("cp.async.commit_group;\n");
    };

    float acc[4][8][4];
#pragma unroll
    for (int i = 0; i < 4; i++)
#pragma unroll
        for (int j = 0; j < 8; j++)
#pragma unroll
            for (int q = 0; q < 4; q++) acc[i][j][q] = 0.f;

    issue(0, 0); issue(1, 1);
    int cur = 0, nxt = 2;
    for (int s = 0; s < NS; s++) {
        if (s < NS - 1) asm volatile("cp.async.wait_group 1;\n");
        else            asm volatile("cp.async.wait_group 0;\n");
        __syncthreads();
        if (s + 2 < NS) issue(s + 2, nxt);
        const float* Asb = sm + cur * ASTG;
        const float* Bsb = sm + 3 * ASTG + cur * BSTG;
#pragma unroll
        for (int kf = 0; kf < 2; kf++) {
            const int kb = kf * 8;
            uint32_t a[4][4], b[8][2];
#pragma unroll
            for (int mt = 0; mt < 4; mt++) {
                int rb = wm * 64 + mt * 16 + g;
                a[mt][0] = __float_as_uint(Asb[rb * 20 + kb + tig]);
                a[mt][1] = __float_as_uint(Asb[(rb + 8) * 20 + kb + tig]);
                a[mt][2] = __float_as_uint(Asb[rb * 20 + kb + tig + 4]);
                a[mt][3] = __float_as_uint(Asb[(rb + 8) * 20 + kb + tig + 4]);
            }
#pragma unroll
            for (int nt = 0; nt < 8; nt++) {
                int cb = wn * 64 + nt * 8 + g;
                b[nt][0] = __float_as_uint(Bsb[(kb + tig) * 136 + cb]);
                b[nt][1] = __float_as_uint(Bsb[(kb + tig + 4) * 136 + cb]);
            }
#pragma unroll
            for (int mt = 0; mt < 4; mt++)
#pragma unroll
                for (int nt = 0; nt < 8; nt++)
                    mma_tf32(acc[mt][nt], a[mt], b[nt]);
        }
        __syncthreads();
        cur = (cur == 2) ? 0 : cur + 1;
        nxt = (nxt == 2) ? 0 : nxt + 1;
    }

    // epilogue: Z = tf32r((acc - theta*B)/delta)
#pragma unroll
    for (int mt = 0; mt < 4; mt++) {
        int r0 = row0 + wm * 64 + mt * 16 + g;
#pragma unroll
        for (int nt = 0; nt < 8; nt++) {
            int c = col0 + wn * 64 + nt * 8 + tig * 2;
            float2 x0 = *(const float2*)(B + (size_t)r0 * NTE + c);
            float2 x1 = *(const float2*)(B + (size_t)(r0 + 8) * NTE + c);
            *(float2*)(Z + (size_t)r0 * NTE + c) = make_float2(
                tf32r((acc[mt][nt][0] - theta * x0.x) * idel),
                tf32r((acc[mt][nt][1] - theta * x0.y) * idel));
            *(float2*)(Z + (size_t)(r0 + 8) * NTE + c) = make_float2(
                tf32r((acc[mt][nt][2] - theta * x1.x) * idel),
                tf32r((acc[mt][nt][3] - theta * x1.y) * idel));
        }
    }
}

// ---- Chebyshev semi-iteration for alpha = K^{-1} y (pure fp32) ----
__global__ void k_cheb_init(const float* __restrict__ y) {
    int i = blockIdx.x * 256 + threadIdx.x;
    if (i >= NTR) return;
    g_xv[i] = 0.f;
    g_rv[i] = y[i];
    g_da[i] = y[i] * g_spec[2];
}

__global__ void k_cheb_iter(const float* __restrict__ din, float* __restrict__ dout, int k) {
    int t = threadIdx.x, lane = t & 31, w = t >> 5;
    int row = blockIdx.x * 8 + w;
    const float* Kr = g_K + (size_t)row * NTR;
    float s = 0.f;
    for (int j = lane; j < NTR; j += 32) s += Kr[j] * din[j];
#pragma unroll
    for (int o = 16; o; o >>= 1) s += __shfl_down_sync(0xffffffffu, s, o);
    if (lane == 0) {
        float dv = din[row];
        g_xv[row] += dv;
        float rv = g_rv[row] - s;
        g_rv[row] = rv;
        dout[row] = g_c1[k] * dv + g_c2[k] * rv;
    }
}

__global__ void k_axpy_final(const float* __restrict__ d) {
    int i = blockIdx.x * 256 + threadIdx.x;
    if (i < NTR) g_xv[i] += d[i];
}

// ---- fused dots: mean partial + 5 moment partials (deg-4) ----
__global__ void k_dots() {            // grid (NTE/128, 8), 128 threads
    __shared__ float sa[512];
    int t = threadIdx.x;
    int n0 = blockIdx.y * 512;
    for (int q = t; q < 512; q += 128) sa[q] = g_xv[n0 + q];
    __syncthreads();
    int m = blockIdx.x * 128 + t;
    float dm = 0, d00 = 0, d01 = 0, d11 = 0, d12 = 0, d22 = 0;
    for (int q = 0; q < 512; q++) {
        size_t off = (size_t)(n0 + q) * NTE + m;
        float kf = g_Ks[off];
        float z1 = g_Z1[off], z2 = g_Z2[off];
        dm  += kf * sa[q];
        d00 += kf * kf; d01 += kf * z1; d11 += z1 * z1;
        d12 += z1 * z2; d22 += z2 * z2;
    }
    g_partM[blockIdx.y * NTE + m] = dm;
    float* pd = g_partD + (size_t)blockIdx.y * 5 * NTE + m;
    pd[0 * NTE] = d00; pd[1 * NTE] = d01; pd[2 * NTE] = d11;
    pd[3 * NTE] = d12; pd[4 * NTE] = d22;
}

__global__ void k_finalize(float* out) {
    int m = blockIdx.x * 256 + threadIdx.x;
    if (m >= NTE) return;
    float sm = 0.f, D[5] = {0, 0, 0, 0, 0};
    for (int p = 0; p < 8; p++) {
        sm += g_partM[p * NTE + m];
        const float* pd = g_partD + (size_t)p * 5 * NTE + m;
#pragma unroll
        for (int j = 0; j < 5; j++) D[j] += pd[j * NTE];
    }
    float q = 0.f;
#pragma unroll
    for (int j = 0; j < 5; j++) q += g_poly[j] * D[j];
    out[m] = sm;
    out[NTE + m] = g_params[0] + g_params[1] - q;
}

// ---- launch ----
extern "C" void kernel_launch(void* const* d_in, const int* in_sizes, int n_in,
                              void* d_out, int out_size)
{
    const float* train_x = (const float*)d_in[0];
    const float* train_y = (const float*)d_in[1];
    const float* test_x  = (const float*)d_in[2];
    const float* lsf2    = (const float*)d_in[3];
    const float* ll2     = (const float*)d_in[4];
    const float* lsn2    = (const float*)d_in[5];
    float* out = (float*)d_out;

    float *pKtf, *pKstf, *pZ1, *pZ2, *pXs, *pTs, *pSqx, *pSqt, *pDa, *pDb;
    cudaGetSymbolAddress((void**)&pKtf,  g_Ktf);
    cudaGetSymbolAddress((void**)&pKstf, g_Kstf);
    cudaGetSymbolAddress((void**)&pZ1,   g_Z1);
    cudaGetSymbolAddress((void**)&pZ2,   g_Z2);
    cudaGetSymbolAddress((void**)&pXs,   g_xs);
    cudaGetSymbolAddress((void**)&pTs,   g_ts);
    cudaGetSymbolAddress((void**)&pSqx,  g_sqx);
    cudaGetSymbolAddress((void**)&pSqt,  g_sqt);
    cudaGetSymbolAddress((void**)&pDa,   g_da);
    cudaGetSymbolAddress((void**)&pDb,   g_db);

    const int smem_gemm = 3 * (128 * 20 + 16 * 136) * sizeof(float);  // 56832
    cudaFuncSetAttribute(k_gemmU, cudaFuncAttributeMaxDynamicSharedMemorySize, smem_gemm);

    k_prep<<<1, 32>>>(lsf2, ll2, lsn2);
    k_scale<<<(NTR + 255) / 256, 256>>>(train_x, pXs, pSqx, NTR);
    k_scale<<<(NTE + 255) / 256, 256>>>(test_x,  pTs, pSqt, NTE);
    k_build_knn<<<dim3(NTR / 32, NTR / 32), 256>>>();
    k_build_ks <<<dim3(NTE / 32, NTR / 32), 256>>>();
    k_rowsum<<<NTR / 8, 256>>>();
    k_spec<<<1, 1024>>>();

    // variance path: Z1 = U*Ks, Z2 = U*Z1  (two big GEMMs, degree-4 poly)
    dim3 ggrid(NTE / 128, NTR / 128);
    k_gemmU<<<ggrid, 128, smem_gemm>>>(pKtf, pKstf, pZ1);
    k_gemmU<<<ggrid, 128, smem_gemm>>>(pKtf, pZ1,   pZ2);

    // mean path: alpha = K^{-1} y via Chebyshev semi-iteration (fp32)
    k_cheb_init<<<(NTR + 255) / 256, 256>>>(train_y);
    float* din = pDa;
    float* dou = pDb;
    for (int k = 1; k <= NIT; k++) {
        k_cheb_iter<<<NTR / 8, 256>>>(din, dou, k);
        float* tmp = din; din = dou; dou = tmp;
    }
    k_axpy_final<<<(NTR + 255) / 256, 256>>>(din);

    k_dots<<<dim3(NTE / 128, 8), 128>>>();
    k_finalize<<<(NTE + 255) / 256, 256>>>(out);
}